// round 14
// baseline (speedup 1.0000x reference)
#include <cuda_runtime.h>
#include <cuda_bf16.h>
#include <math.h>
#include <stdint.h>

// Problem constants
constexpr int BATCH = 4;
constexpr int SEQ   = 2048;
constexpr int DIM   = 1024;
constexpr int NHEAD = 16;
constexpr int HDIM  = 64;
constexpr int NTOK  = BATCH * SEQ;   // 8192
constexpr int BHS   = BATCH * NHEAD; // 64

// Pre-split inputs (hi/lo bf16), row-major [NTOK, DIM]
__device__ __nv_bfloat16 aqh[NTOK * DIM], aql[NTOK * DIM];
__device__ __nv_bfloat16 akh[NTOK * DIM], akl[NTOK * DIM];
__device__ __nv_bfloat16 avh[NTOK * DIM], avl[NTOK * DIM];
// Pre-split weights, row-major [DIM, DIM]
__device__ __nv_bfloat16 wqh[DIM * DIM], wql[DIM * DIM];
__device__ __nv_bfloat16 wkh[DIM * DIM], wkl[DIM * DIM];
__device__ __nv_bfloat16 wvh[DIM * DIM], wvl[DIM * DIM];
__device__ __nv_bfloat16 woh[DIM * DIM], wol[DIM * DIM];
// Post-proj pre-split Q/K/V in [b,h,s,dk]
__device__ __nv_bfloat16 qh_g[BHS * SEQ * HDIM], ql_g[BHS * SEQ * HDIM];
__device__ __nv_bfloat16 kh_g[BHS * SEQ * HDIM], kl_g[BHS * SEQ * HDIM];
__device__ __nv_bfloat16 vh_g[BHS * SEQ * HDIM], vl_g[BHS * SEQ * HDIM];
// Attention output pre-split, [b,s,h*dk]
__device__ __nv_bfloat16 xh_g[NTOK * DIM], xl_g[NTOK * DIM];

// ---------------------------------------------------------------------------
// Helpers
// ---------------------------------------------------------------------------
__device__ __forceinline__ uint32_t smem_u32(const void* p) {
    uint32_t a;
    asm("{ .reg .u64 t; cvta.to.shared.u64 t, %1; cvt.u32.u64 %0, t; }"
        : "=r"(a) : "l"(p));
    return a;
}
__device__ __forceinline__ void ldm_x4(uint32_t* r, uint32_t addr) {
    asm volatile("ldmatrix.sync.aligned.m8n8.x4.shared.b16 {%0,%1,%2,%3}, [%4];"
        : "=r"(r[0]), "=r"(r[1]), "=r"(r[2]), "=r"(r[3]) : "r"(addr));
}
__device__ __forceinline__ void ldm_x4_t(uint32_t* r, uint32_t addr) {
    asm volatile("ldmatrix.sync.aligned.m8n8.x4.trans.shared.b16 {%0,%1,%2,%3}, [%4];"
        : "=r"(r[0]), "=r"(r[1]), "=r"(r[2]), "=r"(r[3]) : "r"(addr));
}
__device__ __forceinline__ void ldm_x2(uint32_t* r, uint32_t addr) {
    asm volatile("ldmatrix.sync.aligned.m8n8.x2.shared.b16 {%0,%1}, [%2];"
        : "=r"(r[0]), "=r"(r[1]) : "r"(addr));
}
__device__ __forceinline__ void mma16816(float* c, const uint32_t* a, const uint32_t* b) {
    asm volatile(
        "mma.sync.aligned.m16n8k16.row.col.f32.bf16.bf16.f32 "
        "{%0,%1,%2,%3}, {%4,%5,%6,%7}, {%8,%9}, {%0,%1,%2,%3};"
        : "+f"(c[0]), "+f"(c[1]), "+f"(c[2]), "+f"(c[3])
        : "r"(a[0]), "r"(a[1]), "r"(a[2]), "r"(a[3]), "r"(b[0]), "r"(b[1]));
}
__device__ __forceinline__ void cvt_hl(float4 v, uint2& hi, uint2& lo) {
    __nv_bfloat162 h0 = __floats2bfloat162_rn(v.x, v.y);
    __nv_bfloat162 h1 = __floats2bfloat162_rn(v.z, v.w);
    float2 f0 = __bfloat1622float2(h0);
    float2 f1 = __bfloat1622float2(h1);
    __nv_bfloat162 l0 = __floats2bfloat162_rn(v.x - f0.x, v.y - f0.y);
    __nv_bfloat162 l1 = __floats2bfloat162_rn(v.z - f1.x, v.w - f1.y);
    hi.x = *(uint32_t*)&h0; hi.y = *(uint32_t*)&h1;
    lo.x = *(uint32_t*)&l0; lo.y = *(uint32_t*)&l1;
}
__device__ __forceinline__ void pack_hl(float a, float b, uint32_t& hi, uint32_t& lo) {
    __nv_bfloat162 h = __floats2bfloat162_rn(a, b);
    float2 hf = __bfloat1622float2(h);
    __nv_bfloat162 l = __floats2bfloat162_rn(a - hf.x, b - hf.y);
    hi = *(uint32_t*)&h;
    lo = *(uint32_t*)&l;
}
// exp2 via MUFU (EX2)
__device__ __forceinline__ float exp2fast(float y) {
    float r;
    asm("ex2.approx.f32 %0, %1;" : "=f"(r) : "f"(y));
    return r;
}

// ---------------------------------------------------------------------------
// Pre-split kernels: fp32 -> (hi, lo) bf16, elementwise
// ---------------------------------------------------------------------------
__global__ void __launch_bounds__(256)
conv_inputs(const float* __restrict__ q, const float* __restrict__ k,
            const float* __restrict__ v)
{
    const int sel = blockIdx.z;
    const float* src = (sel == 0) ? q : (sel == 1) ? k : v;
    __nv_bfloat16* dh = (sel == 0) ? aqh : (sel == 1) ? akh : avh;
    __nv_bfloat16* dl = (sel == 0) ? aql : (sel == 1) ? akl : avl;
    const size_t i = ((size_t)blockIdx.x * 256 + threadIdx.x) * 4;
    float4 val = *(const float4*)(src + i);
    uint2 hi, lo;
    cvt_hl(val, hi, lo);
    *(uint2*)(dh + i) = hi;
    *(uint2*)(dl + i) = lo;
}

__global__ void __launch_bounds__(256)
conv_weights(const float* __restrict__ wq, const float* __restrict__ wk,
             const float* __restrict__ wv, const float* __restrict__ wo)
{
    const int sel = blockIdx.z;
    const float* src = (sel == 0) ? wq : (sel == 1) ? wk : (sel == 2) ? wv : wo;
    __nv_bfloat16* dh = (sel == 0) ? wqh : (sel == 1) ? wkh : (sel == 2) ? wvh : woh;
    __nv_bfloat16* dl = (sel == 0) ? wql : (sel == 1) ? wkl : (sel == 2) ? wvl : wol;
    const size_t i = ((size_t)blockIdx.x * 256 + threadIdx.x) * 4;
    float4 val = *(const float4*)(src + i);
    uint2 hi, lo;
    cvt_hl(val, hi, lo);
    *(uint2*)(dh + i) = hi;
    *(uint2*)(dl + i) = lo;
}

// ===========================================================================
// GEMM v5: R4 schedule, pre-split bf16 inputs (zero conversion in the fill).
// C = A @ W^T, split-3 bf16 HMMA. CTA tile 128x128, 8 warps (2M x 4N),
// warp tile 64x32, K staged 32 wide, register prefetch, single-buffered smem.
// MODE 0: scatter [b,h,s,dk], fused RoPE, pack hi/lo (Q/K projections)
// MODE 1: row-major fp32 (O projection)
// MODE 2: scatter [b,h,s,dk], pack hi/lo (V projection)
// ===========================================================================
constexpr int TKS = 32;
constexpr int NST = DIM / TKS;
constexpr int PITCH = 40;

template <int MODE>
__device__ __forceinline__ void gemm_mma_body(
    const __nv_bfloat16* __restrict__ Ah, const __nv_bfloat16* __restrict__ Al,
    const __nv_bfloat16* __restrict__ Bh, const __nv_bfloat16* __restrict__ Bl,
    float* __restrict__ C,
    __nv_bfloat16* __restrict__ Ch, __nv_bfloat16* __restrict__ Cl)
{
    __shared__ __align__(16) __nv_bfloat16 sAh[128 * PITCH];
    __shared__ __align__(16) __nv_bfloat16 sAl[128 * PITCH];
    __shared__ __align__(16) __nv_bfloat16 sBh[128 * PITCH];
    __shared__ __align__(16) __nv_bfloat16 sBl[128 * PITCH];

    const int tid  = threadIdx.x;
    const int wid  = tid >> 5;
    const int lane = tid & 31;
    const int wm   = wid & 1;
    const int wn   = wid >> 1;
    const int m0   = blockIdx.y * 128;
    const int n0   = blockIdx.x * 128;

    // fill mapping: 2 threads/row; each thread covers 16 bf16 (32B = 2 uint4)
    const int lrow = tid >> 1;
    const int lcol = (tid & 1) * 16;
    const uint4* rah = (const uint4*)(Ah + (size_t)(m0 + lrow) * DIM + lcol);
    const uint4* ral = (const uint4*)(Al + (size_t)(m0 + lrow) * DIM + lcol);
    const uint4* rbh = (const uint4*)(Bh + (size_t)(n0 + lrow) * DIM + lcol);
    const uint4* rbl = (const uint4*)(Bl + (size_t)(n0 + lrow) * DIM + lcol);
    const int soff = lrow * PITCH + lcol;

    const uint32_t aAh = smem_u32(sAh), aAl = smem_u32(sAl);
    const uint32_t aBh = smem_u32(sBh), aBl = smem_u32(sBl);
    const int a_r = wm * 64 + (lane & 15);
    const int a_c = (lane >> 4) * 8;
    const int b_r = wn * 32 + (lane & 7);
    const int b_c = ((lane >> 3) & 1) * 8;

    float acc[4][4][4];
    #pragma unroll
    for (int i = 0; i < 4; i++)
        #pragma unroll
        for (int j = 0; j < 4; j++)
            #pragma unroll
            for (int q = 0; q < 4; q++) acc[i][j][q] = 0.0f;

    // register prefetch buffers: 2 uint4 per array
    uint4 pah[2], pal[2], pbh[2], pbl[2];
    #pragma unroll
    for (int i = 0; i < 2; i++) {
        pah[i] = rah[i]; pal[i] = ral[i];
        pbh[i] = rbh[i]; pbl[i] = rbl[i];
    }
    #pragma unroll
    for (int i = 0; i < 2; i++) {
        *(uint4*)(sAh + soff + i * 8) = pah[i];
        *(uint4*)(sAl + soff + i * 8) = pal[i];
        *(uint4*)(sBh + soff + i * 8) = pbh[i];
        *(uint4*)(sBl + soff + i * 8) = pbl[i];
    }
    __syncthreads();

    for (int s = 0; s < NST; s++) {
        if (s + 1 < NST) {
            const int koff = ((s + 1) * TKS) >> 3;   // uint4 units
            #pragma unroll
            for (int i = 0; i < 2; i++) {
                pah[i] = rah[koff + i]; pal[i] = ral[koff + i];
                pbh[i] = rbh[koff + i]; pbl[i] = rbl[koff + i];
            }
        }
        #pragma unroll
        for (int ks = 0; ks < 2; ks++) {
            uint32_t Ahf[4][4], Alf[4][4], Bhf[4][2], Blf[4][2];
            const int ac = ks * 16 + a_c;
            const int bc = ks * 16 + b_c;
            #pragma unroll
            for (int mi = 0; mi < 4; mi++) {
                const uint32_t off = ((a_r + mi * 16) * PITCH + ac) * 2;
                ldm_x4(Ahf[mi], aAh + off);
                ldm_x4(Alf[mi], aAl + off);
            }
            #pragma unroll
            for (int ni = 0; ni < 4; ni++) {
                const uint32_t off = ((b_r + ni * 8) * PITCH + bc) * 2;
                ldm_x2(Bhf[ni], aBh + off);
                ldm_x2(Blf[ni], aBl + off);
            }
            #pragma unroll
            for (int mi = 0; mi < 4; mi++)
                #pragma unroll
                for (int ni = 0; ni < 4; ni++) {
                    mma16816(acc[mi][ni], Ahf[mi], Bhf[ni]);
                    mma16816(acc[mi][ni], Ahf[mi], Blf[ni]);
                    mma16816(acc[mi][ni], Alf[mi], Bhf[ni]);
                }
        }
        __syncthreads();
        if (s + 1 < NST) {
            #pragma unroll
            for (int i = 0; i < 2; i++) {
                *(uint4*)(sAh + soff + i * 8) = pah[i];
                *(uint4*)(sAl + soff + i * 8) = pal[i];
                *(uint4*)(sBh + soff + i * 8) = pbh[i];
                *(uint4*)(sBl + soff + i * 8) = pbl[i];
            }
            __syncthreads();
        }
    }

    const int er = m0 + wm * 64 + (lane >> 2);
    const int ec = n0 + wn * 32 + (lane & 3) * 2;
    #pragma unroll
    for (int mi = 0; mi < 4; mi++) {
        #pragma unroll
        for (int ni = 0; ni < 4; ni++) {
            const int col = ec + ni * 8;
            #pragma unroll
            for (int half = 0; half < 2; half++) {
                const int row = er + mi * 16 + half * 8;
                float2 v = make_float2(acc[mi][ni][half * 2],
                                       acc[mi][ni][half * 2 + 1]);
                if (MODE == 1) {
                    *(float2*)(C + (size_t)row * DIM + col) = v;
                } else {
                    const int b = row >> 11, sq = row & (SEQ - 1);
                    const int h = col >> 6, dk = col & (HDIM - 1);
                    if (MODE == 0) {
                        // fused RoPE on the interleaved pair (2j, 2j+1)
                        const float e = (float)dk * (1.0f / 64.0f);
                        const float inv_freq = 1.0f / powf(10000.0f, e);
                        float sn, cs;
                        sincosf((float)sq * inv_freq, &sn, &cs);
                        float2 y;
                        y.x = v.x * cs - v.y * sn;
                        y.y = v.y * cs + v.x * sn;
                        v = y;
                    }
                    uint32_t hi, lo;
                    pack_hl(v.x, v.y, hi, lo);
                    const size_t idx = ((size_t)(b * NHEAD + h) * SEQ + sq) * HDIM + dk;
                    *(uint32_t*)(Ch + idx) = hi;
                    *(uint32_t*)(Cl + idx) = lo;
                }
            }
        }
    }
}

__global__ void __launch_bounds__(256, 1)
gemm_qkv_tc()
{
    const int sel = blockIdx.z;
    if (sel == 0)      gemm_mma_body<0>(aqh, aql, wqh, wql, nullptr, qh_g, ql_g);
    else if (sel == 1) gemm_mma_body<0>(akh, akl, wkh, wkl, nullptr, kh_g, kl_g);
    else               gemm_mma_body<2>(avh, avl, wvh, wvl, nullptr, vh_g, vl_g);
}

__global__ void __launch_bounds__(256, 1)
gemm_out_tc(float* __restrict__ out)
{
    gemm_mma_body<1>(xh_g, xl_g, woh, wol, out, nullptr, nullptr);
}

// ===========================================================================
// Tensor-core flash attention (R13: pre-split inputs, pure-copy tile fill).
// Epilogue now packs hi/lo bf16 for the O projection.
// CTA = one (b,h) x 128 q rows. 4 warps x 32 rows. 64-key tiles.
// ===========================================================================
constexpr int QB  = 128;
constexpr int KTL = 64;
constexpr int PQ  = 72;

constexpr int OFF_QH = 0;
constexpr int OFF_QL = OFF_QH + QB * PQ * 2;
constexpr int OFF_KH = OFF_QL + QB * PQ * 2;
constexpr int OFF_KL = OFF_KH + KTL * PQ * 2;
constexpr int OFF_VH = OFF_KL + KTL * PQ * 2;
constexpr int OFF_VL = OFF_VH + KTL * PQ * 2;
constexpr int OFF_MB = OFF_VL + KTL * PQ * 2;
constexpr int SMEM_ATTN = OFF_MB + KTL * 4;

constexpr float SCALE2 = 0.18033688011f;      // 0.125 * log2(e)
constexpr float MBIAS2 = -14426.950409f;      // -10000 * log2(e)

__global__ void __launch_bounds__(128, 1)
attn_mma_kernel(const int* __restrict__ mask)
{
    extern __shared__ char sm[];
    __nv_bfloat16* sQh = (__nv_bfloat16*)(sm + OFF_QH);
    __nv_bfloat16* sQl = (__nv_bfloat16*)(sm + OFF_QL);
    __nv_bfloat16* sKh = (__nv_bfloat16*)(sm + OFF_KH);
    __nv_bfloat16* sKl = (__nv_bfloat16*)(sm + OFF_KL);
    __nv_bfloat16* sVh = (__nv_bfloat16*)(sm + OFF_VH);
    __nv_bfloat16* sVl = (__nv_bfloat16*)(sm + OFF_VL);
    float* sMb = (float*)(sm + OFF_MB);

    const int tid = threadIdx.x;
    const int wid = tid >> 5, lane = tid & 31;
    const int bh = blockIdx.y, b = bh >> 4, h = bh & 15;
    const int q0 = blockIdx.x * QB;

    const size_t qbase  = ((size_t)bh * SEQ + q0) * HDIM;
    const size_t kvbase = (size_t)bh * SEQ * HDIM;

    {
        const uint4* sqh = (const uint4*)(qh_g + qbase + (size_t)tid * HDIM);
        const uint4* sql = (const uint4*)(ql_g + qbase + (size_t)tid * HDIM);
        uint4* dh = (uint4*)(sQh + tid * PQ);
        uint4* dl = (uint4*)(sQl + tid * PQ);
        #pragma unroll
        for (int i = 0; i < 8; i++) {
            dh[i] = sqh[i];
            dl[i] = sql[i];
        }
    }

    float accO[2][8][4];
    #pragma unroll
    for (int mi = 0; mi < 2; mi++)
        #pragma unroll
        for (int ni = 0; ni < 8; ni++)
            #pragma unroll
            for (int v = 0; v < 4; v++) accO[mi][ni][v] = 0.0f;
    float mrow[2][2] = {{-1e30f, -1e30f}, {-1e30f, -1e30f}};
    float lrow[2][2] = {{0.0f, 0.0f}, {0.0f, 0.0f}};

    const int wq0 = wid * 32;
    const uint32_t aQh = smem_u32(sQh), aQl = smem_u32(sQl);
    const uint32_t aKh = smem_u32(sKh), aKl = smem_u32(sKl);
    const uint32_t aVh = smem_u32(sVh), aVl = smem_u32(sVl);

    const int qa = (lane & 15) * PQ + (lane >> 4) * 8;
    const int ka = ((lane & 7) + ((lane >> 4) & 1) * 8) * PQ + ((lane >> 3) & 1) * 8;
    const int va = ((lane & 7) + ((lane >> 3) & 1) * 8) * PQ + ((lane >> 4) & 1) * 8;

    const int ldk  = tid >> 1;
    const int ldc0 = (tid & 1) * 32;

    for (int kt = 0; kt < SEQ; kt += KTL) {
        __syncthreads();
        {
            const size_t goff = kvbase + (size_t)(kt + ldk) * HDIM + ldc0;
            const uint4* skh = (const uint4*)(kh_g + goff);
            const uint4* skl = (const uint4*)(kl_g + goff);
            const uint4* svh = (const uint4*)(vh_g + goff);
            const uint4* svl = (const uint4*)(vl_g + goff);
            uint4* dkh = (uint4*)(sKh + ldk * PQ + ldc0);
            uint4* dkl = (uint4*)(sKl + ldk * PQ + ldc0);
            uint4* dvh = (uint4*)(sVh + ldk * PQ + ldc0);
            uint4* dvl = (uint4*)(sVl + ldk * PQ + ldc0);
            #pragma unroll
            for (int i = 0; i < 4; i++) {
                dkh[i] = skh[i];
                dkl[i] = skl[i];
                dvh[i] = svh[i];
                dvl[i] = svl[i];
            }
            if (tid < KTL)
                sMb[tid] = mask[b * SEQ + kt + tid] ? 0.0f : MBIAS2;
        }
        __syncthreads();

        float bias0[8], bias1[8];
        #pragma unroll
        for (int ni = 0; ni < 8; ni++) {
            bias0[ni] = sMb[ni * 8 + (lane & 3) * 2];
            bias1[ni] = sMb[ni * 8 + (lane & 3) * 2 + 1];
        }

        // ---- S = Q K^T (split-3) ----
        float acc[2][8][4];
        #pragma unroll
        for (int mi = 0; mi < 2; mi++)
            #pragma unroll
            for (int ni = 0; ni < 8; ni++)
                #pragma unroll
                for (int v = 0; v < 4; v++) acc[mi][ni][v] = 0.0f;

        #pragma unroll
        for (int ks = 0; ks < 4; ks++) {
            uint32_t qh[2][4], ql[2][4];
            #pragma unroll
            for (int mi = 0; mi < 2; mi++) {
                const uint32_t off = 2 * ((wq0 + mi * 16) * PQ + ks * 16 + qa);
                ldm_x4(qh[mi], aQh + off);
                ldm_x4(ql[mi], aQl + off);
            }
            #pragma unroll
            for (int nip = 0; nip < 4; nip++) {
                uint32_t kh[4], kl[4];
                const uint32_t off = 2 * (nip * 16 * PQ + ks * 16 + ka);
                ldm_x4(kh, aKh + off);
                ldm_x4(kl, aKl + off);
                #pragma unroll
                for (int mi = 0; mi < 2; mi++)
                    #pragma unroll
                    for (int j = 0; j < 2; j++) {
                        const int ni = nip * 2 + j;
                        mma16816(acc[mi][ni], qh[mi], &kh[2 * j]);
                        mma16816(acc[mi][ni], qh[mi], &kl[2 * j]);
                        mma16816(acc[mi][ni], ql[mi], &kh[2 * j]);
                    }
            }
        }

        // ---- online softmax (exp on MUFU) ----
        #pragma unroll
        for (int mi = 0; mi < 2; mi++) {
            #pragma unroll
            for (int half = 0; half < 2; half++) {
                float mt = -1e30f;
                #pragma unroll
                for (int ni = 0; ni < 8; ni++) {
                    float v0 = fmaf(acc[mi][ni][half * 2],     SCALE2, bias0[ni]);
                    float v1 = fmaf(acc[mi][ni][half * 2 + 1], SCALE2, bias1[ni]);
                    acc[mi][ni][half * 2]     = v0;
                    acc[mi][ni][half * 2 + 1] = v1;
                    mt = fmaxf(mt, fmaxf(v0, v1));
                }
                mt = fmaxf(mt, __shfl_xor_sync(0xFFFFFFFFu, mt, 1));
                mt = fmaxf(mt, __shfl_xor_sync(0xFFFFFFFFu, mt, 2));
                const float mold = mrow[mi][half];
                const float mnew = fmaxf(mold, mt);
                const float corr = exp2fast(mold - mnew);
                mrow[mi][half] = mnew;
                lrow[mi][half] *= corr;
                float lsum = 0.0f;
                #pragma unroll
                for (int ni = 0; ni < 8; ni++) {
                    float p0 = exp2fast(acc[mi][ni][half * 2]     - mnew);
                    float p1 = exp2fast(acc[mi][ni][half * 2 + 1] - mnew);
                    acc[mi][ni][half * 2]     = p0;
                    acc[mi][ni][half * 2 + 1] = p1;
                    lsum += p0 + p1;
                    accO[mi][ni][half * 2]     *= corr;
                    accO[mi][ni][half * 2 + 1] *= corr;
                }
                lrow[mi][half] += lsum;
            }
        }

        // ---- O += P V (full split-3) ----
        #pragma unroll
        for (int kf = 0; kf < 4; kf++) {
            uint32_t pah[2][4], pal[2][4];
            #pragma unroll
            for (int mi = 0; mi < 2; mi++) {
                pack_hl(acc[mi][2 * kf][0],     acc[mi][2 * kf][1],     pah[mi][0], pal[mi][0]);
                pack_hl(acc[mi][2 * kf][2],     acc[mi][2 * kf][3],     pah[mi][1], pal[mi][1]);
                pack_hl(acc[mi][2 * kf + 1][0], acc[mi][2 * kf + 1][1], pah[mi][2], pal[mi][2]);
                pack_hl(acc[mi][2 * kf + 1][2], acc[mi][2 * kf + 1][3], pah[mi][3], pal[mi][3]);
            }
            #pragma unroll
            for (int nip = 0; nip < 4; nip++) {
                uint32_t vh[4], vl[4];
                const uint32_t off = 2 * (kf * 16 * PQ + nip * 16 + va);
                ldm_x4_t(vh, aVh + off);
                ldm_x4_t(vl, aVl + off);
                #pragma unroll
                for (int mi = 0; mi < 2; mi++)
                    #pragma unroll
                    for (int j = 0; j < 2; j++) {
                        const int ni = nip * 2 + j;
                        mma16816(accO[mi][ni], pah[mi], &vh[2 * j]);
                        mma16816(accO[mi][ni], pah[mi], &vl[2 * j]);
                        mma16816(accO[mi][ni], pal[mi], &vh[2 * j]);
                    }
            }
        }
    }

    // ---- epilogue: normalize + pack hi/lo bf16 for the O projection ----
    float inv[2][2];
    #pragma unroll
    for (int mi = 0; mi < 2; mi++)
        #pragma unroll
        for (int half = 0; half < 2; half++) {
            float l = lrow[mi][half];
            l += __shfl_xor_sync(0xFFFFFFFFu, l, 1);
            l += __shfl_xor_sync(0xFFFFFFFFu, l, 2);
            inv[mi][half] = 1.0f / l;
        }

    #pragma unroll
    for (int mi = 0; mi < 2; mi++)
        #pragma unroll
        for (int ni = 0; ni < 8; ni++)
            #pragma unroll
            for (int half = 0; half < 2; half++) {
                const int row = q0 + wq0 + mi * 16 + (lane >> 2) + half * 8;
                const int col = ni * 8 + (lane & 3) * 2;
                const float vx = accO[mi][ni][half * 2] * inv[mi][half];
                const float vy = accO[mi][ni][half * 2 + 1] * inv[mi][half];
                uint32_t hi, lo;
                pack_hl(vx, vy, hi, lo);
                const size_t idx = ((size_t)(b * SEQ + row)) * DIM + h * HDIM + col;
                *(uint32_t*)(xh_g + idx) = hi;
                *(uint32_t*)(xl_g + idx) = lo;
            }
}

// ---------------------------------------------------------------------------
// Launch
// ---------------------------------------------------------------------------
extern "C" void kernel_launch(void* const* d_in, const int* in_sizes, int n_in,
                              void* d_out, int out_size)
{
    const float* q    = (const float*)d_in[0];
    const float* k    = (const float*)d_in[1];
    const float* v    = (const float*)d_in[2];
    const int*   mask = (const int*)  d_in[3];
    const float* w_q  = (const float*)d_in[4];
    const float* w_k  = (const float*)d_in[5];
    const float* w_v  = (const float*)d_in[6];
    const float* w_o  = (const float*)d_in[7];
    float* out = (float*)d_out;

    cudaFuncSetAttribute(attn_mma_kernel,
                         cudaFuncAttributeMaxDynamicSharedMemorySize, SMEM_ATTN);

    // 0) Pre-split inputs and weights into hi/lo bf16 (once)
    conv_inputs<<<dim3(NTOK * DIM / 1024, 1, 3), 256>>>(q, k, v);
    conv_weights<<<dim3(DIM * DIM / 1024, 1, 4), 256>>>(w_q, w_k, w_v, w_o);

    // 1) Q/K/V projections: conversion-free fill, fused RoPE, pre-split out
    dim3 g1(DIM / 128, NTOK / 128, 3);
    gemm_qkv_tc<<<g1, 256>>>();

    // 2) Tensor-core flash attention
    dim3 g3(SEQ / QB, BHS);
    attn_mma_kernel<<<g3, 128, SMEM_ATTN>>>(mask);

    // 3) Output projection (pre-split A from attention epilogue)
    dim3 g4(DIM / 128, NTOK / 128);
    gemm_out_tc<<<g4, 256>>>(out);
}

// round 16
// speedup vs baseline: 1.0367x; 1.0367x over previous
#include <cuda_runtime.h>
#include <cuda_bf16.h>
#include <math.h>
#include <stdint.h>

// Problem constants
constexpr int BATCH = 4;
constexpr int SEQ   = 2048;
constexpr int DIM   = 1024;
constexpr int NHEAD = 16;
constexpr int HDIM  = 64;
constexpr int NTOK  = BATCH * SEQ;   // 8192
constexpr int BHS   = BATCH * NHEAD; // 64

// Scratch: pre-split hi/lo bf16 Q/K/V in [b,h,s,dk]; fp32 attention output.
__device__ __nv_bfloat16 qh_g[BHS * SEQ * HDIM], ql_g[BHS * SEQ * HDIM];
__device__ __nv_bfloat16 kh_g[BHS * SEQ * HDIM], kl_g[BHS * SEQ * HDIM];
__device__ __nv_bfloat16 vh_g[BHS * SEQ * HDIM], vl_g[BHS * SEQ * HDIM];
__device__ float g_x[NTOK * DIM];       // attn out, [b,s,h*dk]

// ---------------------------------------------------------------------------
// Helpers
// ---------------------------------------------------------------------------
__device__ __forceinline__ uint32_t smem_u32(const void* p) {
    uint32_t a;
    asm("{ .reg .u64 t; cvta.to.shared.u64 t, %1; cvt.u32.u64 %0, t; }"
        : "=r"(a) : "l"(p));
    return a;
}
__device__ __forceinline__ void ldm_x4(uint32_t* r, uint32_t addr) {
    asm volatile("ldmatrix.sync.aligned.m8n8.x4.shared.b16 {%0,%1,%2,%3}, [%4];"
        : "=r"(r[0]), "=r"(r[1]), "=r"(r[2]), "=r"(r[3]) : "r"(addr));
}
__device__ __forceinline__ void ldm_x4_t(uint32_t* r, uint32_t addr) {
    asm volatile("ldmatrix.sync.aligned.m8n8.x4.trans.shared.b16 {%0,%1,%2,%3}, [%4];"
        : "=r"(r[0]), "=r"(r[1]), "=r"(r[2]), "=r"(r[3]) : "r"(addr));
}
__device__ __forceinline__ void ldm_x2(uint32_t* r, uint32_t addr) {
    asm volatile("ldmatrix.sync.aligned.m8n8.x2.shared.b16 {%0,%1}, [%2];"
        : "=r"(r[0]), "=r"(r[1]) : "r"(addr));
}
__device__ __forceinline__ void mma16816(float* c, const uint32_t* a, const uint32_t* b) {
    asm volatile(
        "mma.sync.aligned.m16n8k16.row.col.f32.bf16.bf16.f32 "
        "{%0,%1,%2,%3}, {%4,%5,%6,%7}, {%8,%9}, {%0,%1,%2,%3};"
        : "+f"(c[0]), "+f"(c[1]), "+f"(c[2]), "+f"(c[3])
        : "r"(a[0]), "r"(a[1]), "r"(a[2]), "r"(a[3]), "r"(b[0]), "r"(b[1]));
}
__device__ __forceinline__ void cvt_hl(float4 v, uint2& hi, uint2& lo) {
    __nv_bfloat162 h0 = __floats2bfloat162_rn(v.x, v.y);
    __nv_bfloat162 h1 = __floats2bfloat162_rn(v.z, v.w);
    float2 f0 = __bfloat1622float2(h0);
    float2 f1 = __bfloat1622float2(h1);
    __nv_bfloat162 l0 = __floats2bfloat162_rn(v.x - f0.x, v.y - f0.y);
    __nv_bfloat162 l1 = __floats2bfloat162_rn(v.z - f1.x, v.w - f1.y);
    hi.x = *(uint32_t*)&h0; hi.y = *(uint32_t*)&h1;
    lo.x = *(uint32_t*)&l0; lo.y = *(uint32_t*)&l1;
}
__device__ __forceinline__ void pack_hl(float a, float b, uint32_t& hi, uint32_t& lo) {
    __nv_bfloat162 h = __floats2bfloat162_rn(a, b);
    float2 hf = __bfloat1622float2(h);
    __nv_bfloat162 l = __floats2bfloat162_rn(a - hf.x, b - hf.y);
    hi = *(uint32_t*)&h;
    lo = *(uint32_t*)&l;
}
// exp2 via MUFU (EX2)
__device__ __forceinline__ float exp2fast(float y) {
    float r;
    asm("ex2.approx.f32 %0, %1;" : "=f"(r) : "f"(y));
    return r;
}

// ===========================================================================
// GEMM (R4 schedule): C = A @ W^T, split-3 bf16 HMMA.
// CTA tile 128x128, 8 warps (2M x 4N), warp tile 64x32, K staged 32 wide,
// register prefetch, single-buffered smem.
// MODE 0: scatter [b,h,s,dk], fused RoPE, pack hi/lo bf16 (Q/K projections)
// MODE 1: row-major fp32 (O projection)
// MODE 2: scatter [b,h,s,dk], pack hi/lo bf16 (V projection)
// ===========================================================================
constexpr int TKS = 32;
constexpr int NST = DIM / TKS;
constexpr int PITCH = 40;

template <int MODE>
__device__ __forceinline__ void gemm_mma_body(const float* __restrict__ A,
                                              const float* __restrict__ W,
                                              float* __restrict__ C,
                                              __nv_bfloat16* __restrict__ Ch,
                                              __nv_bfloat16* __restrict__ Cl)
{
    __shared__ __align__(16) __nv_bfloat16 sAh[128 * PITCH];
    __shared__ __align__(16) __nv_bfloat16 sAl[128 * PITCH];
    __shared__ __align__(16) __nv_bfloat16 sBh[128 * PITCH];
    __shared__ __align__(16) __nv_bfloat16 sBl[128 * PITCH];

    const int tid  = threadIdx.x;
    const int wid  = tid >> 5;
    const int lane = tid & 31;
    const int wm   = wid & 1;
    const int wn   = wid >> 1;
    const int m0   = blockIdx.y * 128;
    const int n0   = blockIdx.x * 128;

    const int lrow = tid >> 1;
    const int lcol = (tid & 1) * 16;
    const float4* arow = (const float4*)(A + (size_t)(m0 + lrow) * DIM + lcol);
    const float4* brow = (const float4*)(W + (size_t)(n0 + lrow) * DIM + lcol);
    const int soff = lrow * PITCH + lcol;

    const uint32_t aAh = smem_u32(sAh), aAl = smem_u32(sAl);
    const uint32_t aBh = smem_u32(sBh), aBl = smem_u32(sBl);
    const int a_r = wm * 64 + (lane & 15);
    const int a_c = (lane >> 4) * 8;
    const int b_r = wn * 32 + (lane & 7);
    const int b_c = ((lane >> 3) & 1) * 8;

    float acc[4][4][4];
    #pragma unroll
    for (int i = 0; i < 4; i++)
        #pragma unroll
        for (int j = 0; j < 4; j++)
            #pragma unroll
            for (int q = 0; q < 4; q++) acc[i][j][q] = 0.0f;

    float4 ra[4], rb[4];
    #pragma unroll
    for (int i = 0; i < 4; i++) { ra[i] = arow[i]; rb[i] = brow[i]; }
    #pragma unroll
    for (int i = 0; i < 4; i++) {
        uint2 hi, lo;
        cvt_hl(ra[i], hi, lo);
        *(uint2*)(sAh + soff + i * 4) = hi;
        *(uint2*)(sAl + soff + i * 4) = lo;
        cvt_hl(rb[i], hi, lo);
        *(uint2*)(sBh + soff + i * 4) = hi;
        *(uint2*)(sBl + soff + i * 4) = lo;
    }
    __syncthreads();

    for (int s = 0; s < NST; s++) {
        if (s + 1 < NST) {
            const int koff = ((s + 1) * TKS) >> 2;
            #pragma unroll
            for (int i = 0; i < 4; i++) { ra[i] = arow[koff + i]; rb[i] = brow[koff + i]; }
        }
        #pragma unroll
        for (int ks = 0; ks < 2; ks++) {
            uint32_t Ahf[4][4], Alf[4][4], Bhf[4][2], Blf[4][2];
            const int ac = ks * 16 + a_c;
            const int bc = ks * 16 + b_c;
            #pragma unroll
            for (int mi = 0; mi < 4; mi++) {
                const uint32_t off = ((a_r + mi * 16) * PITCH + ac) * 2;
                ldm_x4(Ahf[mi], aAh + off);
                ldm_x4(Alf[mi], aAl + off);
            }
            #pragma unroll
            for (int ni = 0; ni < 4; ni++) {
                const uint32_t off = ((b_r + ni * 8) * PITCH + bc) * 2;
                ldm_x2(Bhf[ni], aBh + off);
                ldm_x2(Blf[ni], aBl + off);
            }
            #pragma unroll
            for (int mi = 0; mi < 4; mi++)
                #pragma unroll
                for (int ni = 0; ni < 4; ni++) {
                    mma16816(acc[mi][ni], Ahf[mi], Bhf[ni]);
                    mma16816(acc[mi][ni], Ahf[mi], Blf[ni]);
                    mma16816(acc[mi][ni], Alf[mi], Bhf[ni]);
                }
        }
        __syncthreads();
        if (s + 1 < NST) {
            #pragma unroll
            for (int i = 0; i < 4; i++) {
                uint2 hi, lo;
                cvt_hl(ra[i], hi, lo);
                *(uint2*)(sAh + soff + i * 4) = hi;
                *(uint2*)(sAl + soff + i * 4) = lo;
                cvt_hl(rb[i], hi, lo);
                *(uint2*)(sBh + soff + i * 4) = hi;
                *(uint2*)(sBl + soff + i * 4) = lo;
            }
            __syncthreads();
        }
    }

    const int er = m0 + wm * 64 + (lane >> 2);
    const int ec = n0 + wn * 32 + (lane & 3) * 2;
    #pragma unroll
    for (int mi = 0; mi < 4; mi++) {
        #pragma unroll
        for (int ni = 0; ni < 4; ni++) {
            const int col = ec + ni * 8;
            #pragma unroll
            for (int half = 0; half < 2; half++) {
                const int row = er + mi * 16 + half * 8;
                float2 v = make_float2(acc[mi][ni][half * 2],
                                       acc[mi][ni][half * 2 + 1]);
                if (MODE == 1) {
                    *(float2*)(C + (size_t)row * DIM + col) = v;
                } else {
                    const int b = row >> 11, sq = row & (SEQ - 1);
                    const int h = col >> 6, dk = col & (HDIM - 1);
                    if (MODE == 0) {
                        // fused RoPE: (v.x, v.y) is the interleaved pair (2j, 2j+1)
                        const float e = (float)dk * (1.0f / 64.0f);
                        const float inv_freq = 1.0f / powf(10000.0f, e);
                        float sn, cs;
                        sincosf((float)sq * inv_freq, &sn, &cs);
                        float2 y;
                        y.x = v.x * cs - v.y * sn;
                        y.y = v.y * cs + v.x * sn;
                        v = y;
                    }
                    uint32_t hi, lo;
                    pack_hl(v.x, v.y, hi, lo);
                    const size_t idx = ((size_t)(b * NHEAD + h) * SEQ + sq) * HDIM + dk;
                    *(uint32_t*)(Ch + idx) = hi;
                    *(uint32_t*)(Cl + idx) = lo;
                }
            }
        }
    }
}

__global__ void __launch_bounds__(256, 1)
gemm_qkv_tc(const float* __restrict__ Aq, const float* __restrict__ Ak,
            const float* __restrict__ Av, const float* __restrict__ Wq,
            const float* __restrict__ Wk, const float* __restrict__ Wv)
{
    const int sel = blockIdx.z;
    if (sel == 0)      gemm_mma_body<0>(Aq, Wq, nullptr, qh_g, ql_g);
    else if (sel == 1) gemm_mma_body<0>(Ak, Wk, nullptr, kh_g, kl_g);
    else               gemm_mma_body<2>(Av, Wv, nullptr, vh_g, vl_g);
}

__global__ void __launch_bounds__(256, 1)
gemm_out_tc(const float* __restrict__ Wo, float* __restrict__ C)
{
    gemm_mma_body<1>(g_x, Wo, C, nullptr, nullptr);
}

// ===========================================================================
// Tensor-core flash attention (R13 numerics; 2 CTAs/SM).
// CTA = one (b,h) x 128 q rows. 4 warps x 32 rows. 64-key tiles.
// ===========================================================================
constexpr int QB  = 128;
constexpr int KTL = 64;
constexpr int PQ  = 72;

constexpr int OFF_QH = 0;
constexpr int OFF_QL = OFF_QH + QB * PQ * 2;
constexpr int OFF_KH = OFF_QL + QB * PQ * 2;
constexpr int OFF_KL = OFF_KH + KTL * PQ * 2;
constexpr int OFF_VH = OFF_KL + KTL * PQ * 2;
constexpr int OFF_VL = OFF_VH + KTL * PQ * 2;
constexpr int OFF_MB = OFF_VL + KTL * PQ * 2;
constexpr int SMEM_ATTN = OFF_MB + KTL * 4;

constexpr float SCALE2 = 0.18033688011f;      // 0.125 * log2(e)
constexpr float MBIAS2 = -14426.950409f;      // -10000 * log2(e)

__global__ void __launch_bounds__(128, 2)
attn_mma_kernel(const int* __restrict__ mask)
{
    extern __shared__ char sm[];
    __nv_bfloat16* sQh = (__nv_bfloat16*)(sm + OFF_QH);
    __nv_bfloat16* sQl = (__nv_bfloat16*)(sm + OFF_QL);
    __nv_bfloat16* sKh = (__nv_bfloat16*)(sm + OFF_KH);
    __nv_bfloat16* sKl = (__nv_bfloat16*)(sm + OFF_KL);
    __nv_bfloat16* sVh = (__nv_bfloat16*)(sm + OFF_VH);
    __nv_bfloat16* sVl = (__nv_bfloat16*)(sm + OFF_VL);
    float* sMb = (float*)(sm + OFF_MB);

    const int tid = threadIdx.x;
    const int wid = tid >> 5, lane = tid & 31;
    const int bh = blockIdx.y, b = bh >> 4, h = bh & 15;
    const int q0 = blockIdx.x * QB;

    const size_t qbase  = ((size_t)bh * SEQ + q0) * HDIM;
    const size_t kvbase = (size_t)bh * SEQ * HDIM;

    // ---- load Q block (pre-split): pure copy, row = tid ----
    {
        const uint4* sqh = (const uint4*)(qh_g + qbase + (size_t)tid * HDIM);
        const uint4* sql = (const uint4*)(ql_g + qbase + (size_t)tid * HDIM);
        uint4* dh = (uint4*)(sQh + tid * PQ);
        uint4* dl = (uint4*)(sQl + tid * PQ);
        #pragma unroll
        for (int i = 0; i < 8; i++) {
            dh[i] = sqh[i];
            dl[i] = sql[i];
        }
    }

    float accO[2][8][4];
    #pragma unroll
    for (int mi = 0; mi < 2; mi++)
        #pragma unroll
        for (int ni = 0; ni < 8; ni++)
            #pragma unroll
            for (int v = 0; v < 4; v++) accO[mi][ni][v] = 0.0f;
    float mrow[2][2] = {{-1e30f, -1e30f}, {-1e30f, -1e30f}};
    float lrow[2][2] = {{0.0f, 0.0f}, {0.0f, 0.0f}};

    const int wq0 = wid * 32;
    const uint32_t aQh = smem_u32(sQh), aQl = smem_u32(sQl);
    const uint32_t aKh = smem_u32(sKh), aKl = smem_u32(sKl);
    const uint32_t aVh = smem_u32(sVh), aVl = smem_u32(sVl);

    const int qa = (lane & 15) * PQ + (lane >> 4) * 8;
    const int ka = ((lane & 7) + ((lane >> 4) & 1) * 8) * PQ + ((lane >> 3) & 1) * 8;
    const int va = ((lane & 7) + ((lane >> 3) & 1) * 8) * PQ + ((lane >> 4) & 1) * 8;

    const int ldk  = tid >> 1;
    const int ldc0 = (tid & 1) * 32;

    for (int kt = 0; kt < SEQ; kt += KTL) {
        __syncthreads();
        {
            const size_t goff = kvbase + (size_t)(kt + ldk) * HDIM + ldc0;
            const uint4* skh = (const uint4*)(kh_g + goff);
            const uint4* skl = (const uint4*)(kl_g + goff);
            const uint4* svh = (const uint4*)(vh_g + goff);
            const uint4* svl = (const uint4*)(vl_g + goff);
            uint4* dkh = (uint4*)(sKh + ldk * PQ + ldc0);
            uint4* dkl = (uint4*)(sKl + ldk * PQ + ldc0);
            uint4* dvh = (uint4*)(sVh + ldk * PQ + ldc0);
            uint4* dvl = (uint4*)(sVl + ldk * PQ + ldc0);
            #pragma unroll
            for (int i = 0; i < 4; i++) {
                dkh[i] = skh[i];
                dkl[i] = skl[i];
                dvh[i] = svh[i];
                dvl[i] = svl[i];
            }
            if (tid < KTL)
                sMb[tid] = mask[b * SEQ + kt + tid] ? 0.0f : MBIAS2;
        }
        __syncthreads();

        float bias0[8], bias1[8];
        #pragma unroll
        for (int ni = 0; ni < 8; ni++) {
            bias0[ni] = sMb[ni * 8 + (lane & 3) * 2];
            bias1[ni] = sMb[ni * 8 + (lane & 3) * 2 + 1];
        }

        // ---- S = Q K^T (split-3) ----
        float acc[2][8][4];
        #pragma unroll
        for (int mi = 0; mi < 2; mi++)
            #pragma unroll
            for (int ni = 0; ni < 8; ni++)
                #pragma unroll
                for (int v = 0; v < 4; v++) acc[mi][ni][v] = 0.0f;

        #pragma unroll
        for (int ks = 0; ks < 4; ks++) {
            uint32_t qh[2][4], ql[2][4];
            #pragma unroll
            for (int mi = 0; mi < 2; mi++) {
                const uint32_t off = 2 * ((wq0 + mi * 16) * PQ + ks * 16 + qa);
                ldm_x4(qh[mi], aQh + off);
                ldm_x4(ql[mi], aQl + off);
            }
            #pragma unroll
            for (int nip = 0; nip < 4; nip++) {
                uint32_t kh[4], kl[4];
                const uint32_t off = 2 * (nip * 16 * PQ + ks * 16 + ka);
                ldm_x4(kh, aKh + off);
                ldm_x4(kl, aKl + off);
                #pragma unroll
                for (int mi = 0; mi < 2; mi++)
                    #pragma unroll
                    for (int j = 0; j < 2; j++) {
                        const int ni = nip * 2 + j;
                        mma16816(acc[mi][ni], qh[mi], &kh[2 * j]);
                        mma16816(acc[mi][ni], qh[mi], &kl[2 * j]);
                        mma16816(acc[mi][ni], ql[mi], &kh[2 * j]);
                    }
            }
        }

        // ---- online softmax (exp on MUFU) ----
        #pragma unroll
        for (int mi = 0; mi < 2; mi++) {
            #pragma unroll
            for (int half = 0; half < 2; half++) {
                float mt = -1e30f;
                #pragma unroll
                for (int ni = 0; ni < 8; ni++) {
                    float v0 = fmaf(acc[mi][ni][half * 2],     SCALE2, bias0[ni]);
                    float v1 = fmaf(acc[mi][ni][half * 2 + 1], SCALE2, bias1[ni]);
                    acc[mi][ni][half * 2]     = v0;
                    acc[mi][ni][half * 2 + 1] = v1;
                    mt = fmaxf(mt, fmaxf(v0, v1));
                }
                mt = fmaxf(mt, __shfl_xor_sync(0xFFFFFFFFu, mt, 1));
                mt = fmaxf(mt, __shfl_xor_sync(0xFFFFFFFFu, mt, 2));
                const float mold = mrow[mi][half];
                const float mnew = fmaxf(mold, mt);
                const float corr = exp2fast(mold - mnew);
                mrow[mi][half] = mnew;
                lrow[mi][half] *= corr;
                float lsum = 0.0f;
                #pragma unroll
                for (int ni = 0; ni < 8; ni++) {
                    float p0 = exp2fast(acc[mi][ni][half * 2]     - mnew);
                    float p1 = exp2fast(acc[mi][ni][half * 2 + 1] - mnew);
                    acc[mi][ni][half * 2]     = p0;
                    acc[mi][ni][half * 2 + 1] = p1;
                    lsum += p0 + p1;
                    accO[mi][ni][half * 2]     *= corr;
                    accO[mi][ni][half * 2 + 1] *= corr;
                }
                lrow[mi][half] += lsum;
            }
        }

        // ---- O += P V (full split-3) ----
        #pragma unroll
        for (int kf = 0; kf < 4; kf++) {
            uint32_t pah[2][4], pal[2][4];
            #pragma unroll
            for (int mi = 0; mi < 2; mi++) {
                pack_hl(acc[mi][2 * kf][0],     acc[mi][2 * kf][1],     pah[mi][0], pal[mi][0]);
                pack_hl(acc[mi][2 * kf][2],     acc[mi][2 * kf][3],     pah[mi][1], pal[mi][1]);
                pack_hl(acc[mi][2 * kf + 1][0], acc[mi][2 * kf + 1][1], pah[mi][2], pal[mi][2]);
                pack_hl(acc[mi][2 * kf + 1][2], acc[mi][2 * kf + 1][3], pah[mi][3], pal[mi][3]);
            }
            #pragma unroll
            for (int nip = 0; nip < 4; nip++) {
                uint32_t vh[4], vl[4];
                const uint32_t off = 2 * (kf * 16 * PQ + nip * 16 + va);
                ldm_x4_t(vh, aVh + off);
                ldm_x4_t(vl, aVl + off);
                #pragma unroll
                for (int mi = 0; mi < 2; mi++)
                    #pragma unroll
                    for (int j = 0; j < 2; j++) {
                        const int ni = nip * 2 + j;
                        mma16816(accO[mi][ni], pah[mi], &vh[2 * j]);
                        mma16816(accO[mi][ni], pah[mi], &vl[2 * j]);
                        mma16816(accO[mi][ni], pal[mi], &vh[2 * j]);
                    }
            }
        }
    }

    // ---- epilogue ----
    float inv[2][2];
    #pragma unroll
    for (int mi = 0; mi < 2; mi++)
        #pragma unroll
        for (int half = 0; half < 2; half++) {
            float l = lrow[mi][half];
            l += __shfl_xor_sync(0xFFFFFFFFu, l, 1);
            l += __shfl_xor_sync(0xFFFFFFFFu, l, 2);
            inv[mi][half] = 1.0f / l;
        }

    #pragma unroll
    for (int mi = 0; mi < 2; mi++)
        #pragma unroll
        for (int ni = 0; ni < 8; ni++)
            #pragma unroll
            for (int half = 0; half < 2; half++) {
                const int row = q0 + wq0 + mi * 16 + (lane >> 2) + half * 8;
                const int col = ni * 8 + (lane & 3) * 2;
                float2 v = make_float2(accO[mi][ni][half * 2] * inv[mi][half],
                                       accO[mi][ni][half * 2 + 1] * inv[mi][half]);
                *(float2*)(g_x + ((size_t)(b * SEQ + row)) * DIM + h * HDIM + col) = v;
            }
}

// ---------------------------------------------------------------------------
// Launch
// ---------------------------------------------------------------------------
extern "C" void kernel_launch(void* const* d_in, const int* in_sizes, int n_in,
                              void* d_out, int out_size)
{
    const float* q    = (const float*)d_in[0];
    const float* k    = (const float*)d_in[1];
    const float* v    = (const float*)d_in[2];
    const int*   mask = (const int*)  d_in[3];
    const float* w_q  = (const float*)d_in[4];
    const float* w_k  = (const float*)d_in[5];
    const float* w_v  = (const float*)d_in[6];
    const float* w_o  = (const float*)d_in[7];
    float* out = (float*)d_out;

    cudaFuncSetAttribute(attn_mma_kernel,
                         cudaFuncAttributeMaxDynamicSharedMemorySize, SMEM_ATTN);

    // 1) Q/K/V projections: fused RoPE (Q/K) + hi/lo bf16 pre-split outputs
    dim3 g1(DIM / 128, NTOK / 128, 3);
    gemm_qkv_tc<<<g1, 256>>>(q, k, v, w_q, w_k, w_v);

    // 2) Tensor-core flash attention (2 CTAs/SM)
    dim3 g3(SEQ / QB, BHS);
    attn_mma_kernel<<<g3, 128, SMEM_ATTN>>>(mask);

    // 3) Output projection
    dim3 g4(DIM / 128, NTOK / 128);
    gemm_out_tc<<<g4, 256>>>(w_o, out);
}